// round 5
// baseline (speedup 1.0000x reference)
#include <cuda_runtime.h>
#include <cuda_bf16.h>
#include <math.h>

// MovingNormalizationLayer: 1-D moving-window (w=100) normalization along the
// last axis of [1,1,128,256,1024] fp32. Zero-padded window, denominator = 100
// everywhere -> clamped prefix-sum differences.
//
// R1/R2: eliminate shared-memory bank conflicts.
//  - compute phase uses strided mapping i = t + 256k  -> lane-consecutive LDS
//  - exclusive-prefix layout lets each thread write its 4 P / P2 entries as a
//    single aligned STS.128 each (conflict-free)

#define ROW_LEN 1024
#define WIN 100
#define HALF_L 50
#define THREADS 256

__device__ __forceinline__ float fixup(float r) {
    // jnp.nan_to_num defaults: nan->0, +inf->FLT_MAX, -inf->-FLT_MAX
    if (isnan(r)) return 0.0f;
    if (isinf(r)) return (r > 0.0f) ? 3.4028234663852886e38f : -3.4028234663852886e38f;
    return r;
}

__global__ __launch_bounds__(THREADS, 8)
void moving_norm_kernel(const float* __restrict__ x, float* __restrict__ out) {
    __shared__ float sx[ROW_LEN];
    __shared__ float P [ROW_LEN + 4];   // exclusive prefix: P[i] = sum x[0..i)
    __shared__ float P2[ROW_LEN + 4];
    __shared__ float wsum [THREADS / 32];
    __shared__ float wsum2[THREADS / 32];

    const int t    = threadIdx.x;
    const int lane = t & 31;
    const int wid  = t >> 5;
    const size_t row_off = (size_t)blockIdx.x * ROW_LEN;

    // ---- coalesced float4 load of this thread's 4 contiguous elements ----
    const float4 v = reinterpret_cast<const float4*>(x + row_off)[t];
    reinterpret_cast<float4*>(sx)[t] = v;          // conflict-free STS.128

    const float s  = v.x + v.y + v.z + v.w;
    const float s2 = v.x * v.x + v.y * v.y + v.z * v.z + v.w * v.w;

    // ---- warp inclusive scan (pair) ----
    float inc = s, inc2 = s2;
    #pragma unroll
    for (int off = 1; off < 32; off <<= 1) {
        const float a = __shfl_up_sync(0xffffffffu, inc,  off);
        const float b = __shfl_up_sync(0xffffffffu, inc2, off);
        if (lane >= off) { inc += a; inc2 += b; }
    }
    if (lane == 31) { wsum[wid] = inc; wsum2[wid] = inc2; }
    __syncthreads();

    float woff = 0.0f, woff2 = 0.0f;
    #pragma unroll
    for (int w = 0; w < THREADS / 32; ++w) {
        if (w < wid) { woff += wsum[w]; woff2 += wsum2[w]; }
    }
    const float excl  = woff  + inc  - s;    // exclusive prefix before 4t
    const float excl2 = woff2 + inc2 - s2;

    // ---- write exclusive prefixes for positions 4t..4t+3 as one STS.128 each ----
    {
        float4 p, q;
        p.x = excl;
        p.y = p.x + v.x;
        p.z = p.y + v.y;
        p.w = p.z + v.z;
        q.x = excl2;
        q.y = q.x + v.x * v.x;
        q.z = q.y + v.y * v.y;
        q.w = q.z + v.z * v.z;
        reinterpret_cast<float4*>(P )[t] = p;   // aligned, conflict-free
        reinterpret_cast<float4*>(P2)[t] = q;
        if (t == THREADS - 1) {                 // total sums -> P[1024]
            P [ROW_LEN] = excl  + s;
            P2[ROW_LEN] = excl2 + s2;
        }
    }
    __syncthreads();

    // ---- compute, strided mapping: lanes read consecutive shared addresses ----
    const float inv_n = 1.0f / (float)WIN;
    #pragma unroll
    for (int k = 0; k < 4; ++k) {
        const int i  = t + k * THREADS;
        const int lo = (i - HALF_L > 0)       ? (i - HALF_L) : 0;
        const int hi = (i + HALF_L < ROW_LEN) ? (i + HALF_L) : ROW_LEN;
        const float mean  = (P [hi] - P [lo]) * inv_n;
        const float mean2 = (P2[hi] - P2[lo]) * inv_n;
        const float stdv  = sqrtf(mean2 - mean * mean);
        const float r  = (sx[i] - mean) / stdv;
        out[row_off + i] = fixup(r);             // coalesced STG.32
    }
}

extern "C" void kernel_launch(void* const* d_in, const int* in_sizes, int n_in,
                              void* d_out, int out_size) {
    const float* x = (const float*)d_in[0];
    float* out = (float*)d_out;
    const int total = in_sizes[0];          // 33,554,432
    const int rows  = total / ROW_LEN;      // 32,768
    moving_norm_kernel<<<rows, THREADS>>>(x, out);
}

// round 8
// speedup vs baseline: 1.1076x; 1.1076x over previous
#include <cuda_runtime.h>
#include <cuda_bf16.h>
#include <math.h>

// MovingNormalizationLayer: 1-D moving-window (w=100) normalization along the
// last axis of [1,1,128,256,1024] fp32. Zero-padded window, denominator = 100
// everywhere -> clamped prefix-sum differences.
//
// R5-R7: instruction-count reduction (kernel was issue-bound at 87.6%).
//  - padded prefix arrays (50 zeros left, 50 totals right): no clamping, and
//    both window endpoints for the 4t..4t+3 group are aligned float4 LDS.128
//  - compute mapping == load mapping, so x stays in registers (sx eliminated)
//  - one STG.128 per thread; rsqrtf*mul instead of sqrt+div

#define ROW_LEN 1024
#define WIN 100
#define HALF_L 50
#define THREADS 256
#define PAD_N (HALF_L + ROW_LEN + HALF_L + 4)   // 50 + 1024 + 50 + pad = 1128

__device__ __forceinline__ float fixup(float r) {
    // jnp.nan_to_num defaults: nan->0, +inf->FLT_MAX, -inf->-FLT_MAX
    if (isnan(r)) return 0.0f;
    if (isinf(r)) return (r > 0.0f) ? 3.4028234663852886e38f : -3.4028234663852886e38f;
    return r;
}

__device__ __forceinline__ float norm1(float xv, float slo, float shi,
                                       float qlo, float qhi) {
    // window sum / sum-of-squares via prefix diff; n = 100
    const float sum  = shi - slo;
    const float sum2 = qhi - qlo;
    const float mean = sum * (1.0f / (float)WIN);
    // var = sum2/n - mean^2
    const float var  = fmaf(sum2, (1.0f / (float)WIN), -mean * mean);
    return fixup((xv - mean) * rsqrtf(var));
}

__global__ __launch_bounds__(THREADS, 8)
void moving_norm_kernel(const float* __restrict__ x, float* __restrict__ out) {
    __shared__ __align__(16) float P [PAD_N];  // P [50+i] = sum x[0..i)
    __shared__ __align__(16) float P2[PAD_N];
    __shared__ float wsum [THREADS / 32];
    __shared__ float wsum2[THREADS / 32];

    const int t    = threadIdx.x;
    const int lane = t & 31;
    const int wid  = t >> 5;
    const size_t row_off = (size_t)blockIdx.x * ROW_LEN;

    // ---- coalesced float4 load of this thread's 4 contiguous elements ----
    const float4 v = reinterpret_cast<const float4*>(x + row_off)[t];

    const float s  = v.x + v.y + v.z + v.w;
    const float s2 = v.x * v.x + v.y * v.y + v.z * v.z + v.w * v.w;

    // left pads (independent of data)
    if (t < HALF_L) { P[t] = 0.0f; P2[t] = 0.0f; }

    // ---- warp inclusive scan (pair) ----
    float inc = s, inc2 = s2;
    #pragma unroll
    for (int off = 1; off < 32; off <<= 1) {
        const float a = __shfl_up_sync(0xffffffffu, inc,  off);
        const float b = __shfl_up_sync(0xffffffffu, inc2, off);
        if (lane >= off) { inc += a; inc2 += b; }
    }
    if (lane == 31) { wsum[wid] = inc; wsum2[wid] = inc2; }
    __syncthreads();

    // prefix over warps + row totals (8 iters, all threads)
    float woff = 0.0f, woff2 = 0.0f, tot = 0.0f, tot2 = 0.0f;
    #pragma unroll
    for (int w = 0; w < THREADS / 32; ++w) {
        const float a = wsum[w], b = wsum2[w];
        tot += a; tot2 += b;
        if (w < wid) { woff += a; woff2 += b; }
    }
    const float excl  = woff  + inc  - s;    // exclusive prefix before 4t
    const float excl2 = woff2 + inc2 - s2;

    // ---- write prefixes for positions 4t..4t+3 (base offset 50 -> 2x STS.64) ----
    {
        float2 a0, a1, b0, b1;
        a0.x = excl;
        a0.y = a0.x + v.x;
        a1.x = a0.y + v.y;
        a1.y = a1.x + v.z;
        b0.x = excl2;
        b0.y = b0.x + v.x * v.x;
        b1.x = b0.y + v.y * v.y;
        b1.y = b1.x + v.z * v.z;
        float2* pp = reinterpret_cast<float2*>(&P [HALF_L + 4 * t]);
        float2* qq = reinterpret_cast<float2*>(&P2[HALF_L + 4 * t]);
        pp[0] = a0; pp[1] = a1;
        qq[0] = b0; qq[1] = b1;
    }
    // right pads: indices 1074..1123 hold P[1024] = total
    if (t < HALF_L) {
        P [HALF_L + ROW_LEN + t] = tot;
        P2[HALF_L + ROW_LEN + t] = tot2;
    }
    __syncthreads();

    // ---- compute: both window endpoints are aligned float4 reads ----
    // out[i] window sum = P[i+50] - P[i-50]  (i = 4t+k)
    //   lo group: Ppad[4t..4t+3]        (byte 16t)
    //   hi group: Ppad[4t+100..4t+103]  (byte 16t+400, 16B-aligned)
    const float4 plo = *reinterpret_cast<const float4*>(&P [4 * t]);
    const float4 phi = *reinterpret_cast<const float4*>(&P [4 * t + 2 * HALF_L]);
    const float4 qlo = *reinterpret_cast<const float4*>(&P2[4 * t]);
    const float4 qhi = *reinterpret_cast<const float4*>(&P2[4 * t + 2 * HALF_L]);

    float4 o;
    o.x = norm1(v.x, plo.x, phi.x, qlo.x, qhi.x);
    o.y = norm1(v.y, plo.y, phi.y, qlo.y, qhi.y);
    o.z = norm1(v.z, plo.z, phi.z, qlo.z, qhi.z);
    o.w = norm1(v.w, plo.w, phi.w, qlo.w, qhi.w);
    reinterpret_cast<float4*>(out + row_off)[t] = o;
}

extern "C" void kernel_launch(void* const* d_in, const int* in_sizes, int n_in,
                              void* d_out, int out_size) {
    const float* x = (const float*)d_in[0];
    float* out = (float*)d_out;
    const int total = in_sizes[0];          // 33,554,432
    const int rows  = total / ROW_LEN;      // 32,768
    moving_norm_kernel<<<rows, THREADS>>>(x, out);
}

// round 10
// speedup vs baseline: 1.2064x; 1.0892x over previous
#include <cuda_runtime.h>
#include <cuda_bf16.h>
#include <math.h>

// MovingNormalizationLayer: 1-D moving-window (w=100) normalization along the
// last axis of [1,1,128,256,1024] fp32. Zero-padded window, denominator = 100
// everywhere -> clamped prefix-sum differences.
//
// R9: R7 layout (separate P/P2, conflict-free 16B-stride accesses) +
//  - warp partial sums as float2[8] read via 4 broadcast LDS.128
//    (replaces 16 scalar LDS per thread)
//  - vectorized pad writes; totals computed only by pad threads
//  - branchless nan/inf fixup

#define ROW_LEN 1024
#define WIN 100
#define HALF_L 50
#define THREADS 256
#define PAD_N (HALF_L + ROW_LEN + HALF_L + 4)   // 1128
#define FLT_MAX_C 3.4028234663852886e38f

__device__ __forceinline__ float fixup(float r) {
    r = (r != r) ? 0.0f : r;                       // nan -> 0
    return fminf(fmaxf(r, -FLT_MAX_C), FLT_MAX_C); // +/-inf -> +/-FLT_MAX
}

__device__ __forceinline__ float norm1(float xv, float slo, float shi,
                                       float qlo, float qhi) {
    const float sum  = shi - slo;
    const float sum2 = qhi - qlo;
    const float mean = sum * (1.0f / (float)WIN);
    const float var  = fmaf(sum2, (1.0f / (float)WIN), -mean * mean);
    return fixup((xv - mean) * rsqrtf(var));
}

__global__ __launch_bounds__(THREADS, 8)
void moving_norm_kernel(const float* __restrict__ x, float* __restrict__ out) {
    __shared__ __align__(16) float P [PAD_N];   // P [50+i] = sum x[0..i)
    __shared__ __align__(16) float P2[PAD_N];
    __shared__ __align__(16) float2 ws[THREADS / 32];   // (warp sum, warp sum2)

    const int t    = threadIdx.x;
    const int lane = t & 31;
    const int wid  = t >> 5;
    const int row_off = (int)(blockIdx.x << 10);

    // ---- coalesced float4 load of this thread's 4 contiguous elements ----
    const float4 v = reinterpret_cast<const float4*>(x + row_off)[t];

    const float xx = v.x * v.x, yy = v.y * v.y, zz = v.z * v.z, ww = v.w * v.w;
    const float s  = v.x + v.y + v.z + v.w;
    const float s2 = xx + yy + zz + ww;

    // left pads: 50 zeros per array -> 25 threads x STS.64 each
    if (t < HALF_L / 2) {
        reinterpret_cast<float2*>(P )[t] = make_float2(0.f, 0.f);
        reinterpret_cast<float2*>(P2)[t] = make_float2(0.f, 0.f);
    }

    // ---- warp inclusive scan (pair) ----
    float inc = s, inc2 = s2;
    #pragma unroll
    for (int off = 1; off < 32; off <<= 1) {
        const float a = __shfl_up_sync(0xffffffffu, inc,  off);
        const float b = __shfl_up_sync(0xffffffffu, inc2, off);
        if (lane >= off) { inc += a; inc2 += b; }
    }
    if (lane == 31) ws[wid] = make_float2(inc, inc2);
    __syncthreads();

    // warp partials via 4 broadcast LDS.128
    const float4 wa = reinterpret_cast<const float4*>(ws)[0];  // warps 0,1
    const float4 wb = reinterpret_cast<const float4*>(ws)[1];  // warps 2,3
    const float4 wc = reinterpret_cast<const float4*>(ws)[2];  // warps 4,5
    const float4 wd = reinterpret_cast<const float4*>(ws)[3];  // warps 6,7

    float woff = 0.f, woff2 = 0.f;
    if (wid > 0) { woff += wa.x; woff2 += wa.y; }
    if (wid > 1) { woff += wa.z; woff2 += wa.w; }
    if (wid > 2) { woff += wb.x; woff2 += wb.y; }
    if (wid > 3) { woff += wb.z; woff2 += wb.w; }
    if (wid > 4) { woff += wc.x; woff2 += wc.y; }
    if (wid > 5) { woff += wc.z; woff2 += wc.w; }
    if (wid > 6) { woff += wd.x; woff2 += wd.y; }

    const float excl  = woff  + inc  - s;    // exclusive prefix before 4t
    const float excl2 = woff2 + inc2 - s2;

    // ---- write prefixes for positions 4t..4t+3 (base 50 -> 2x STS.64 each) ----
    {
        float2 a0, a1, b0, b1;
        a0.x = excl;
        a0.y = a0.x + v.x;
        a1.x = a0.y + v.y;
        a1.y = a1.x + v.z;
        b0.x = excl2;
        b0.y = b0.x + xx;
        b1.x = b0.y + yy;
        b1.y = b1.x + zz;
        float2* pp = reinterpret_cast<float2*>(&P [HALF_L + 4 * t]);
        float2* qq = reinterpret_cast<float2*>(&P2[HALF_L + 4 * t]);
        pp[0] = a0; pp[1] = a1;
        qq[0] = b0; qq[1] = b1;
    }
    // right pads: entries 1074..1123 hold row totals -> 25 threads x STS.64 each
    if (t < HALF_L / 2) {
        const float T  = wa.x + wa.z + wb.x + wb.z + wc.x + wc.z + wd.x + wd.z;
        const float T2 = wa.y + wa.w + wb.y + wb.w + wc.y + wc.w + wd.y + wd.w;
        reinterpret_cast<float2*>(&P [HALF_L + ROW_LEN])[t] = make_float2(T,  T);
        reinterpret_cast<float2*>(&P2[HALF_L + ROW_LEN])[t] = make_float2(T2, T2);
    }
    __syncthreads();

    // ---- compute: 4 aligned, conflict-free LDS.128 ----
    // out[i] window sum = P[i+50] - P[i-50]  (i = 4t+k)
    //   lo: Ppad[4t..4t+3]       (byte 16t)
    //   hi: Ppad[4t+100..4t+103] (byte 16t+400, 16B-aligned)
    const float4 plo = *reinterpret_cast<const float4*>(&P [4 * t]);
    const float4 phi = *reinterpret_cast<const float4*>(&P [4 * t + 2 * HALF_L]);
    const float4 qlo = *reinterpret_cast<const float4*>(&P2[4 * t]);
    const float4 qhi = *reinterpret_cast<const float4*>(&P2[4 * t + 2 * HALF_L]);

    float4 o;
    o.x = norm1(v.x, plo.x, phi.x, qlo.x, qhi.x);
    o.y = norm1(v.y, plo.y, phi.y, qlo.y, qhi.y);
    o.z = norm1(v.z, plo.z, phi.z, qlo.z, qhi.z);
    o.w = norm1(v.w, plo.w, phi.w, qlo.w, qhi.w);
    reinterpret_cast<float4*>(out + row_off)[t] = o;
}

extern "C" void kernel_launch(void* const* d_in, const int* in_sizes, int n_in,
                              void* d_out, int out_size) {
    const float* x = (const float*)d_in[0];
    float* out = (float*)d_out;
    const int total = in_sizes[0];          // 33,554,432
    const int rows  = total / ROW_LEN;      // 32,768
    moving_norm_kernel<<<rows, THREADS>>>(x, out);
}